// round 1
// baseline (speedup 1.0000x reference)
#include <cuda_runtime.h>
#include <cuda_bf16.h>

// Problem constants
#define B_ 4
#define S_ 2048
#define D_ 1024
#define H_ 16
#define DK_ 64
#define SCALE_ 0.125f   // 1/sqrt(64)

#define M_ROWS (B_ * S_)   // 8192

// ---------------- scratch (device globals; no allocation allowed) ----------
__device__ float g_q[B_ * H_ * S_ * DK_];    // [B,H,S,DK]
__device__ float g_k[B_ * H_ * S_ * DK_];
__device__ float g_v[B_ * H_ * S_ * DK_];
__device__ float g_att[B_ * S_ * D_];        // [B,S,D]

// ---------------- SGEMM: C = A[M,K] @ W[K,N] + bias --------------------------
// MODE 0: write C row-major [M,N]
// MODE 1: write C into [B,H,S,DK] layout (n -> head*64+dk, m -> b*S+s)
template <int MODE>
__global__ __launch_bounds__(256)
void sgemm_bias_kernel(const float* __restrict__ A, const float* __restrict__ W,
                       const float* __restrict__ bias, float* __restrict__ C,
                       int M, int N, int K)
{
    const int BM = 128, BN = 128, BK = 8, TM = 8, TN = 8;
    __shared__ float As[BK][BM];
    __shared__ float Bs[BK][BN];

    const int block_row = blockIdx.y;
    const int block_col = blockIdx.x;
    const int tid = threadIdx.x;          // 0..255
    const int tx = tid % 16;
    const int ty = tid / 16;

    // global->shared load indices
    const int a_row = tid >> 1;           // 0..127
    const int a_col = (tid & 1) * 4;      // 0 or 4
    const int b_row = tid >> 5;           // 0..7
    const int b_col = (tid & 31) * 4;     // 0..124

    const float* Ab = A + (size_t)block_row * BM * K;
    const float* Wb = W + block_col * BN;

    float acc[TM][TN];
    #pragma unroll
    for (int i = 0; i < TM; i++)
        #pragma unroll
        for (int j = 0; j < TN; j++) acc[i][j] = 0.f;

    float regM[TM], regN[TN];

    for (int k0 = 0; k0 < K; k0 += BK) {
        float4 av = *(const float4*)(Ab + (size_t)a_row * K + k0 + a_col);
        As[a_col + 0][a_row] = av.x;
        As[a_col + 1][a_row] = av.y;
        As[a_col + 2][a_row] = av.z;
        As[a_col + 3][a_row] = av.w;
        *(float4*)(&Bs[b_row][b_col]) =
            *(const float4*)(Wb + (size_t)(k0 + b_row) * N + b_col);
        __syncthreads();

        #pragma unroll
        for (int k = 0; k < BK; k++) {
            #pragma unroll
            for (int i = 0; i < TM; i++) regM[i] = As[k][ty * TM + i];
            #pragma unroll
            for (int j = 0; j < TN; j++) regN[j] = Bs[k][tx * TN + j];
            #pragma unroll
            for (int i = 0; i < TM; i++)
                #pragma unroll
                for (int j = 0; j < TN; j++)
                    acc[i][j] += regM[i] * regN[j];
        }
        __syncthreads();
    }

    // epilogue
    #pragma unroll
    for (int i = 0; i < TM; i++) {
        const int m = block_row * BM + ty * TM + i;
        #pragma unroll
        for (int j = 0; j < TN; j++) {
            const int n = block_col * BN + tx * TN + j;
            float val = acc[i][j] + bias[n];
            if (MODE == 0) {
                C[(size_t)m * N + n] = val;
            } else {
                const int b  = m >> 11;     // m / 2048
                const int s  = m & 2047;
                const int h  = n >> 6;      // n / 64
                const int dk = n & 63;
                C[(((size_t)(b * H_ + h)) * S_ + s) * DK_ + dk] = val;
            }
        }
    }
}

// ---------------- causal flash attention (fp32) ------------------------------
// grid: (S/64, B*H), 128 threads. Each thread pair (2 threads) owns one q row:
//   half hf owns dk range [hf*32, hf*32+32) of the output, and computes scores
//   for key columns j in [hf*32, hf*32+32) of each 64-wide key tile.
__global__ __launch_bounds__(128)
void flash_attn_kernel(const float* __restrict__ q, const float* __restrict__ k,
                       const float* __restrict__ v, float* __restrict__ o)
{
    __shared__ float Ks[64][64];
    __shared__ float Vs[64][64];

    const int qt  = blockIdx.x;
    const int bh  = blockIdx.y;
    const int tid = threadIdx.x;
    const int r   = tid >> 1;       // q row within tile (0..63)
    const int hf  = tid & 1;        // half
    const int q0  = qt * 64;

    const float* qb = q + (size_t)bh * S_ * DK_;
    const float* kb = k + (size_t)bh * S_ * DK_;
    const float* vb = v + (size_t)bh * S_ * DK_;

    // Q row (own dk half) into registers, pre-scaled
    float qreg[32];
    {
        const float* qrow = qb + (size_t)(q0 + r) * DK_ + hf * 32;
        #pragma unroll
        for (int i = 0; i < 8; i++) {
            float4 t = *(const float4*)(qrow + i * 4);
            qreg[i * 4 + 0] = t.x * SCALE_;
            qreg[i * 4 + 1] = t.y * SCALE_;
            qreg[i * 4 + 2] = t.z * SCALE_;
            qreg[i * 4 + 3] = t.w * SCALE_;
        }
    }

    float O[32];
    #pragma unroll
    for (int i = 0; i < 32; i++) O[i] = 0.f;
    float m = -INFINITY;
    float l = 0.f;

    for (int kt = 0; kt <= qt; kt++) {
        const int k0 = kt * 64;
        __syncthreads();   // everyone done reading previous K/V
        // load K,V tiles (64x64 each), coalesced float4
        for (int idx = tid; idx < 64 * 16; idx += 128) {
            const int row = idx >> 4;
            const int c4  = (idx & 15) * 4;
            *(float4*)&Ks[row][c4] = *(const float4*)(kb + (size_t)(k0 + row) * DK_ + c4);
            *(float4*)&Vs[row][c4] = *(const float4*)(vb + (size_t)(k0 + row) * DK_ + c4);
        }
        __syncthreads();

        // --- scores for this tile; sp holds s, then p in-place ---
        float sp[32];
        #pragma unroll
        for (int jj = 0; jj < 32; jj++) {
            const int ja = jj;        // half-0 column
            const int jb = 32 + jj;   // half-1 column
            float pa = 0.f, pb = 0.f;
            #pragma unroll
            for (int d = 0; d < 32; d += 4) {
                float4 ka  = *(const float4*)&Ks[ja][hf * 32 + d];
                float4 kb4 = *(const float4*)&Ks[jb][hf * 32 + d];
                pa += qreg[d] * ka.x + qreg[d + 1] * ka.y +
                      qreg[d + 2] * ka.z + qreg[d + 3] * ka.w;
                pb += qreg[d] * kb4.x + qreg[d + 1] * kb4.y +
                      qreg[d + 2] * kb4.z + qreg[d + 3] * kb4.w;
            }
            // exchange partials with pair partner (lane ^ 1)
            const float mine  = hf == 0 ? pa : pb;
            const float send  = hf == 0 ? pb : pa;
            const float recv  = __shfl_xor_sync(0xffffffffu, send, 1);
            float s = mine + recv;
            // causal mask (only bites on the diagonal tile)
            if (k0 + hf * 32 + jj > q0 + r) s = -1e30f;
            sp[jj] = s;
        }

        // --- online softmax update ---
        float mloc = -INFINITY;
        #pragma unroll
        for (int jj = 0; jj < 32; jj++) mloc = fmaxf(mloc, sp[jj]);
        mloc = fmaxf(mloc, __shfl_xor_sync(0xffffffffu, mloc, 1));
        const float mnew  = fmaxf(m, mloc);
        const float alpha = __expf(m - mnew);
        float lsum = 0.f;
        #pragma unroll
        for (int jj = 0; jj < 32; jj++) {
            const float p = __expf(sp[jj] - mnew);
            sp[jj] = p;
            lsum += p;
        }
        l = l * alpha + lsum;
        m = mnew;
        #pragma unroll
        for (int d = 0; d < 32; d++) O[d] *= alpha;

        // --- O += P @ V (own dk half, all 64 columns via pair exchange) ---
        #pragma unroll
        for (int jj = 0; jj < 32; jj++) {
            const float pown  = sp[jj];
            const float precv = __shfl_xor_sync(0xffffffffu, pown, 1);
            const int j_own = hf * 32 + jj;
            const int j_oth = (hf ^ 1) * 32 + jj;
            #pragma unroll
            for (int d = 0; d < 32; d += 4) {
                float4 va  = *(const float4*)&Vs[j_own][hf * 32 + d];
                float4 vb4 = *(const float4*)&Vs[j_oth][hf * 32 + d];
                O[d + 0] += pown * va.x + precv * vb4.x;
                O[d + 1] += pown * va.y + precv * vb4.y;
                O[d + 2] += pown * va.z + precv * vb4.z;
                O[d + 3] += pown * va.w + precv * vb4.w;
            }
        }
    }

    // finalize: combine pair l, normalize, write into [B,S,D] layout
    const float ltot = l + __shfl_xor_sync(0xffffffffu, l, 1);
    const float inv  = 1.f / ltot;
    const int b = bh >> 4;
    const int h = bh & 15;
    float* orow = o + ((size_t)b * S_ + q0 + r) * D_ + h * DK_ + hf * 32;
    #pragma unroll
    for (int d = 0; d < 32; d += 4) {
        float4 t;
        t.x = O[d + 0] * inv;
        t.y = O[d + 1] * inv;
        t.z = O[d + 2] * inv;
        t.w = O[d + 3] * inv;
        *(float4*)(orow + d) = t;
    }
}

// ---------------- launch ------------------------------------------------------
extern "C" void kernel_launch(void* const* d_in, const int* in_sizes, int n_in,
                              void* d_out, int out_size)
{
    const float* Q  = (const float*)d_in[0];
    const float* K  = (const float*)d_in[1];
    const float* V  = (const float*)d_in[2];
    const float* Wq = (const float*)d_in[3];
    const float* bq = (const float*)d_in[4];
    const float* Wk = (const float*)d_in[5];
    const float* bk = (const float*)d_in[6];
    const float* Wv = (const float*)d_in[7];
    const float* bv = (const float*)d_in[8];
    const float* Wo = (const float*)d_in[9];
    const float* bo = (const float*)d_in[10];
    // d_in[11] = mask (causal, known statically; ignored)

    float *q, *k, *v, *att;
    cudaGetSymbolAddress((void**)&q,   g_q);
    cudaGetSymbolAddress((void**)&k,   g_k);
    cudaGetSymbolAddress((void**)&v,   g_v);
    cudaGetSymbolAddress((void**)&att, g_att);

    const dim3 gemm_grid(D_ / 128, M_ROWS / 128);   // (8, 64)
    const dim3 gemm_block(256);

    // QKV projections -> [B,H,S,DK]
    sgemm_bias_kernel<1><<<gemm_grid, gemm_block>>>(Q, Wq, bq, q, M_ROWS, D_, D_);
    sgemm_bias_kernel<1><<<gemm_grid, gemm_block>>>(K, Wk, bk, k, M_ROWS, D_, D_);
    sgemm_bias_kernel<1><<<gemm_grid, gemm_block>>>(V, Wv, bv, v, M_ROWS, D_, D_);

    // causal flash attention -> [B,S,D]
    const dim3 fa_grid(S_ / 64, B_ * H_);
    flash_attn_kernel<<<fa_grid, 128>>>(q, k, v, att);

    // output projection -> d_out [B*S, D]
    sgemm_bias_kernel<0><<<gemm_grid, gemm_block>>>(att, Wo, bo, (float*)d_out,
                                                    M_ROWS, D_, D_);
}

// round 2
// speedup vs baseline: 1.3342x; 1.3342x over previous
#include <cuda_runtime.h>
#include <cuda_bf16.h>
#include <cstdint>

// Problem constants
#define B_ 4
#define S_ 2048
#define D_ 1024
#define H_ 16
#define DK_ 64
#define SCALE_ 0.125f   // 1/sqrt(64)

#define M_ROWS (B_ * S_)   // 8192

// ---------------- scratch (device globals; no allocation allowed) ----------
__device__ float g_q[B_ * H_ * S_ * DK_];    // [B,H,S,DK]
__device__ float g_k[B_ * H_ * S_ * DK_];
__device__ float g_v[B_ * H_ * S_ * DK_];
__device__ float g_att[B_ * S_ * D_];        // [B,S,D]

// ---------------- tf32 helpers ----------------------------------------------
__device__ __forceinline__ uint32_t f2tf32(float f) {
    uint32_t r;
    asm("cvt.rna.tf32.f32 %0, %1;" : "=r"(r) : "f"(f));
    return r;
}

__device__ __forceinline__ void mma_tf32_16x8x8(
    float& c0, float& c1, float& c2, float& c3,
    uint32_t a0, uint32_t a1, uint32_t a2, uint32_t a3,
    uint32_t b0, uint32_t b1)
{
    asm volatile(
        "mma.sync.aligned.m16n8k8.row.col.f32.tf32.tf32.f32 "
        "{%0,%1,%2,%3}, {%4,%5,%6,%7}, {%8,%9}, {%0,%1,%2,%3};"
        : "+f"(c0), "+f"(c1), "+f"(c2), "+f"(c3)
        : "r"(a0), "r"(a1), "r"(a2), "r"(a3), "r"(b0), "r"(b1));
}

// ---------------- tf32 tensor-core GEMM: C = A[M,K] @ W[K,N] + bias ----------
// 128x128x16 block tile, 256 threads = 8 warps (2x4), warp tile 64x32.
// MODE 0: write C row-major [M,N]
// MODE 1: write C into [B,H,S,DK] layout (n -> head*64+dk, m -> b*S+s)
#define GBM 128
#define GBN 128
#define GBK 16
#define AS_STR (GBK + 4)    // 20 floats: frag banks = 4*(k%4) + m%8 -> conflict-free
#define BS_STR (GBN + 8)    // 136 floats: frag banks = 8*(k%4) + n%8 -> conflict-free

template <int MODE>
__global__ __launch_bounds__(256)
void gemm_tf32_kernel(const float* __restrict__ A, const float* __restrict__ W,
                      const float* __restrict__ bias, float* __restrict__ C,
                      int M, int N, int K)
{
    __shared__ uint32_t As[GBM * AS_STR];   // [m][k], tf32 bits
    __shared__ uint32_t Bs[GBK * BS_STR];   // [k][n], tf32 bits

    const int tid  = threadIdx.x;
    const int warp = tid >> 5;
    const int lane = tid & 31;
    const int warpM = warp >> 2;            // 0..1  -> 64-row slice
    const int warpN = warp & 3;             // 0..3  -> 32-col slice
    const int lr = lane >> 2;               // lane / 4 (0..7)
    const int lc = lane & 3;                // lane % 4 (0..3)

    const int block_row = blockIdx.y;
    const int block_col = blockIdx.x;

    // global->shared load indices (each thread: 8 floats of A, 8 floats of B)
    const int a_row = tid >> 1;             // 0..127
    const int a_col = (tid & 1) * 8;        // 0 or 8
    const int b_row = tid >> 4;             // 0..15
    const int b_col = (tid & 15) * 8;       // 0..120

    const float* Ab = A + (size_t)block_row * GBM * K;
    const float* Wb = W + block_col * GBN;

    float acc[4][4][4];
    #pragma unroll
    for (int mt = 0; mt < 4; mt++)
        #pragma unroll
        for (int nt = 0; nt < 4; nt++)
            #pragma unroll
            for (int r = 0; r < 4; r++) acc[mt][nt][r] = 0.f;

    for (int k0 = 0; k0 < K; k0 += GBK) {
        // load + convert A tile (128x16) into As[m][k]
        {
            const float* src = Ab + (size_t)a_row * K + k0 + a_col;
            float4 v0 = *(const float4*)(src);
            float4 v1 = *(const float4*)(src + 4);
            uint32_t* dst = &As[a_row * AS_STR + a_col];
            dst[0] = f2tf32(v0.x); dst[1] = f2tf32(v0.y);
            dst[2] = f2tf32(v0.z); dst[3] = f2tf32(v0.w);
            dst[4] = f2tf32(v1.x); dst[5] = f2tf32(v1.y);
            dst[6] = f2tf32(v1.z); dst[7] = f2tf32(v1.w);
        }
        // load + convert B tile (16x128) into Bs[k][n]
        {
            const float* src = Wb + (size_t)(k0 + b_row) * N + b_col;
            float4 v0 = *(const float4*)(src);
            float4 v1 = *(const float4*)(src + 4);
            uint32_t* dst = &Bs[b_row * BS_STR + b_col];
            dst[0] = f2tf32(v0.x); dst[1] = f2tf32(v0.y);
            dst[2] = f2tf32(v0.z); dst[3] = f2tf32(v0.w);
            dst[4] = f2tf32(v1.x); dst[5] = f2tf32(v1.y);
            dst[6] = f2tf32(v1.z); dst[7] = f2tf32(v1.w);
        }
        __syncthreads();

        #pragma unroll
        for (int ks = 0; ks < GBK; ks += 8) {
            uint32_t af[4][4];
            #pragma unroll
            for (int mt = 0; mt < 4; mt++) {
                const int m0 = warpM * 64 + mt * 16;
                af[mt][0] = As[(m0 + lr)     * AS_STR + ks + lc];
                af[mt][1] = As[(m0 + 8 + lr) * AS_STR + ks + lc];
                af[mt][2] = As[(m0 + lr)     * AS_STR + ks + 4 + lc];
                af[mt][3] = As[(m0 + 8 + lr) * AS_STR + ks + 4 + lc];
            }
            uint32_t bf[4][2];
            #pragma unroll
            for (int nt = 0; nt < 4; nt++) {
                const int n0 = warpN * 32 + nt * 8;
                bf[nt][0] = Bs[(ks + lc)     * BS_STR + n0 + lr];
                bf[nt][1] = Bs[(ks + 4 + lc) * BS_STR + n0 + lr];
            }
            #pragma unroll
            for (int mt = 0; mt < 4; mt++)
                #pragma unroll
                for (int nt = 0; nt < 4; nt++)
                    mma_tf32_16x8x8(acc[mt][nt][0], acc[mt][nt][1],
                                    acc[mt][nt][2], acc[mt][nt][3],
                                    af[mt][0], af[mt][1], af[mt][2], af[mt][3],
                                    bf[nt][0], bf[nt][1]);
        }
        __syncthreads();
    }

    // epilogue: c0,c1 -> (row, 2*lc), (row, 2*lc+1); c2,c3 -> row+8
    #pragma unroll
    for (int mt = 0; mt < 4; mt++) {
        #pragma unroll
        for (int nt = 0; nt < 4; nt++) {
            const int n = block_col * GBN + warpN * 32 + nt * 8 + lc * 2;
            #pragma unroll
            for (int half = 0; half < 2; half++) {
                const int m = block_row * GBM + warpM * 64 + mt * 16 + lr + half * 8;
                const float v0 = acc[mt][nt][half * 2 + 0] + bias[n];
                const float v1 = acc[mt][nt][half * 2 + 1] + bias[n + 1];
                if (MODE == 0) {
                    *(float2*)&C[(size_t)m * N + n] = make_float2(v0, v1);
                } else {
                    const int b  = m >> 11;
                    const int s  = m & 2047;
                    const int h  = n >> 6;
                    const int dk = n & 63;
                    float* dst = &g_q[0]; // dummy init; overwritten below
                    dst = C + (((size_t)(b * H_ + h)) * S_ + s) * DK_ + dk;
                    *(float2*)dst = make_float2(v0, v1);
                }
            }
        }
    }
}

// ---------------- causal flash attention (fp32) ------------------------------
__global__ __launch_bounds__(128)
void flash_attn_kernel(const float* __restrict__ q, const float* __restrict__ k,
                       const float* __restrict__ v, float* __restrict__ o)
{
    __shared__ float Ks[64][64];
    __shared__ float Vs[64][64];

    const int qt  = blockIdx.x;
    const int bh  = blockIdx.y;
    const int tid = threadIdx.x;
    const int r   = tid >> 1;
    const int hf  = tid & 1;
    const int q0  = qt * 64;

    const float* qb = q + (size_t)bh * S_ * DK_;
    const float* kb = k + (size_t)bh * S_ * DK_;
    const float* vb = v + (size_t)bh * S_ * DK_;

    float qreg[32];
    {
        const float* qrow = qb + (size_t)(q0 + r) * DK_ + hf * 32;
        #pragma unroll
        for (int i = 0; i < 8; i++) {
            float4 t = *(const float4*)(qrow + i * 4);
            qreg[i * 4 + 0] = t.x * SCALE_;
            qreg[i * 4 + 1] = t.y * SCALE_;
            qreg[i * 4 + 2] = t.z * SCALE_;
            qreg[i * 4 + 3] = t.w * SCALE_;
        }
    }

    float O[32];
    #pragma unroll
    for (int i = 0; i < 32; i++) O[i] = 0.f;
    float m = -INFINITY;
    float l = 0.f;

    for (int kt = 0; kt <= qt; kt++) {
        const int k0 = kt * 64;
        __syncthreads();
        for (int idx = tid; idx < 64 * 16; idx += 128) {
            const int row = idx >> 4;
            const int c4  = (idx & 15) * 4;
            *(float4*)&Ks[row][c4] = *(const float4*)(kb + (size_t)(k0 + row) * DK_ + c4);
            *(float4*)&Vs[row][c4] = *(const float4*)(vb + (size_t)(k0 + row) * DK_ + c4);
        }
        __syncthreads();

        float sp[32];
        #pragma unroll
        for (int jj = 0; jj < 32; jj++) {
            const int ja = jj;
            const int jb = 32 + jj;
            float pa = 0.f, pb = 0.f;
            #pragma unroll
            for (int d = 0; d < 32; d += 4) {
                float4 ka  = *(const float4*)&Ks[ja][hf * 32 + d];
                float4 kb4 = *(const float4*)&Ks[jb][hf * 32 + d];
                pa += qreg[d] * ka.x + qreg[d + 1] * ka.y +
                      qreg[d + 2] * ka.z + qreg[d + 3] * ka.w;
                pb += qreg[d] * kb4.x + qreg[d + 1] * kb4.y +
                      qreg[d + 2] * kb4.z + qreg[d + 3] * kb4.w;
            }
            const float mine  = hf == 0 ? pa : pb;
            const float send  = hf == 0 ? pb : pa;
            const float recv  = __shfl_xor_sync(0xffffffffu, send, 1);
            float s = mine + recv;
            if (k0 + hf * 32 + jj > q0 + r) s = -1e30f;
            sp[jj] = s;
        }

        float mloc = -INFINITY;
        #pragma unroll
        for (int jj = 0; jj < 32; jj++) mloc = fmaxf(mloc, sp[jj]);
        mloc = fmaxf(mloc, __shfl_xor_sync(0xffffffffu, mloc, 1));
        const float mnew  = fmaxf(m, mloc);
        const float alpha = __expf(m - mnew);
        float lsum = 0.f;
        #pragma unroll
        for (int jj = 0; jj < 32; jj++) {
            const float p = __expf(sp[jj] - mnew);
            sp[jj] = p;
            lsum += p;
        }
        l = l * alpha + lsum;
        m = mnew;
        #pragma unroll
        for (int d = 0; d < 32; d++) O[d] *= alpha;

        #pragma unroll
        for (int jj = 0; jj < 32; jj++) {
            const float pown  = sp[jj];
            const float precv = __shfl_xor_sync(0xffffffffu, pown, 1);
            const int j_own = hf * 32 + jj;
            const int j_oth = (hf ^ 1) * 32 + jj;
            #pragma unroll
            for (int d = 0; d < 32; d += 4) {
                float4 va  = *(const float4*)&Vs[j_own][hf * 32 + d];
                float4 vb4 = *(const float4*)&Vs[j_oth][hf * 32 + d];
                O[d + 0] += pown * va.x + precv * vb4.x;
                O[d + 1] += pown * va.y + precv * vb4.y;
                O[d + 2] += pown * va.z + precv * vb4.z;
                O[d + 3] += pown * va.w + precv * vb4.w;
            }
        }
    }

    const float ltot = l + __shfl_xor_sync(0xffffffffu, l, 1);
    const float inv  = 1.f / ltot;
    const int b = bh >> 4;
    const int h = bh & 15;
    float* orow = o + ((size_t)b * S_ + q0 + r) * D_ + h * DK_ + hf * 32;
    #pragma unroll
    for (int d = 0; d < 32; d += 4) {
        float4 t;
        t.x = O[d + 0] * inv;
        t.y = O[d + 1] * inv;
        t.z = O[d + 2] * inv;
        t.w = O[d + 3] * inv;
        *(float4*)(orow + d) = t;
    }
}

// ---------------- launch ------------------------------------------------------
extern "C" void kernel_launch(void* const* d_in, const int* in_sizes, int n_in,
                              void* d_out, int out_size)
{
    const float* Q  = (const float*)d_in[0];
    const float* K  = (const float*)d_in[1];
    const float* V  = (const float*)d_in[2];
    const float* Wq = (const float*)d_in[3];
    const float* bq = (const float*)d_in[4];
    const float* Wk = (const float*)d_in[5];
    const float* bk = (const float*)d_in[6];
    const float* Wv = (const float*)d_in[7];
    const float* bv = (const float*)d_in[8];
    const float* Wo = (const float*)d_in[9];
    const float* bo = (const float*)d_in[10];
    // d_in[11] = mask (causal, known statically; ignored)

    float *q, *k, *v, *att;
    cudaGetSymbolAddress((void**)&q,   g_q);
    cudaGetSymbolAddress((void**)&k,   g_k);
    cudaGetSymbolAddress((void**)&v,   g_v);
    cudaGetSymbolAddress((void**)&att, g_att);

    const dim3 gemm_grid(D_ / GBN, M_ROWS / GBM);   // (8, 64)
    const dim3 gemm_block(256);

    // QKV projections -> [B,H,S,DK]
    gemm_tf32_kernel<1><<<gemm_grid, gemm_block>>>(Q, Wq, bq, q, M_ROWS, D_, D_);
    gemm_tf32_kernel<1><<<gemm_grid, gemm_block>>>(K, Wk, bk, k, M_ROWS, D_, D_);
    gemm_tf32_kernel<1><<<gemm_grid, gemm_block>>>(V, Wv, bv, v, M_ROWS, D_, D_);

    // causal flash attention -> [B,S,D]
    const dim3 fa_grid(S_ / 64, B_ * H_);
    flash_attn_kernel<<<fa_grid, 128>>>(q, k, v, att);

    // output projection -> d_out [B*S, D]
    gemm_tf32_kernel<0><<<gemm_grid, gemm_block>>>(att, Wo, bo, (float*)d_out,
                                                   M_ROWS, D_, D_);
}

// round 3
// speedup vs baseline: 3.4100x; 2.5559x over previous
#include <cuda_runtime.h>
#include <cuda_bf16.h>
#include <cstdint>

// Problem constants
#define B_ 4
#define S_ 2048
#define D_ 1024
#define H_ 16
#define DK_ 64
#define SCALE_ 0.125f   // 1/sqrt(64)

#define M_ROWS (B_ * S_)   // 8192

// ---------------- scratch (device globals; no allocation allowed) ----------
__device__ float g_q[B_ * H_ * S_ * DK_];    // [B,H,S,DK]
__device__ float g_k[B_ * H_ * S_ * DK_];
__device__ float g_v[B_ * H_ * S_ * DK_];
__device__ float g_att[B_ * S_ * D_];        // [B,S,D]

// ---------------- tf32 helpers ----------------------------------------------
__device__ __forceinline__ uint32_t f2tf32(float f) {
    uint32_t r;
    asm("cvt.rna.tf32.f32 %0, %1;" : "=r"(r) : "f"(f));
    return r;
}

__device__ __forceinline__ void mma_tf32_16x8x8(
    float& c0, float& c1, float& c2, float& c3,
    uint32_t a0, uint32_t a1, uint32_t a2, uint32_t a3,
    uint32_t b0, uint32_t b1)
{
    asm volatile(
        "mma.sync.aligned.m16n8k8.row.col.f32.tf32.tf32.f32 "
        "{%0,%1,%2,%3}, {%4,%5,%6,%7}, {%8,%9}, {%0,%1,%2,%3};"
        : "+f"(c0), "+f"(c1), "+f"(c2), "+f"(c3)
        : "r"(a0), "r"(a1), "r"(a2), "r"(a3), "r"(b0), "r"(b1));
}

// ---------------- tf32 tensor-core GEMM: C = A[M,K] @ W[K,N] + bias ----------
#define GBM 128
#define GBN 128
#define GBK 16
#define AS_STR (GBK + 4)    // 20
#define BS_STR (GBN + 8)    // 136

template <int MODE>
__global__ __launch_bounds__(256)
void gemm_tf32_kernel(const float* __restrict__ A, const float* __restrict__ W,
                      const float* __restrict__ bias, float* __restrict__ C,
                      int M, int N, int K)
{
    __shared__ uint32_t As[GBM * AS_STR];
    __shared__ uint32_t Bs[GBK * BS_STR];

    const int tid  = threadIdx.x;
    const int warp = tid >> 5;
    const int lane = tid & 31;
    const int warpM = warp >> 2;
    const int warpN = warp & 3;
    const int lr = lane >> 2;
    const int lc = lane & 3;

    const int block_row = blockIdx.y;
    const int block_col = blockIdx.x;

    const int a_row = tid >> 1;
    const int a_col = (tid & 1) * 8;
    const int b_row = tid >> 4;
    const int b_col = (tid & 15) * 8;

    const float* Ab = A + (size_t)block_row * GBM * K;
    const float* Wb = W + block_col * GBN;

    float acc[4][4][4];
    #pragma unroll
    for (int mt = 0; mt < 4; mt++)
        #pragma unroll
        for (int nt = 0; nt < 4; nt++)
            #pragma unroll
            for (int r = 0; r < 4; r++) acc[mt][nt][r] = 0.f;

    for (int k0 = 0; k0 < K; k0 += GBK) {
        {
            const float* src = Ab + (size_t)a_row * K + k0 + a_col;
            float4 v0 = *(const float4*)(src);
            float4 v1 = *(const float4*)(src + 4);
            uint32_t* dst = &As[a_row * AS_STR + a_col];
            dst[0] = f2tf32(v0.x); dst[1] = f2tf32(v0.y);
            dst[2] = f2tf32(v0.z); dst[3] = f2tf32(v0.w);
            dst[4] = f2tf32(v1.x); dst[5] = f2tf32(v1.y);
            dst[6] = f2tf32(v1.z); dst[7] = f2tf32(v1.w);
        }
        {
            const float* src = Wb + (size_t)(k0 + b_row) * N + b_col;
            float4 v0 = *(const float4*)(src);
            float4 v1 = *(const float4*)(src + 4);
            uint32_t* dst = &Bs[b_row * BS_STR + b_col];
            dst[0] = f2tf32(v0.x); dst[1] = f2tf32(v0.y);
            dst[2] = f2tf32(v0.z); dst[3] = f2tf32(v0.w);
            dst[4] = f2tf32(v1.x); dst[5] = f2tf32(v1.y);
            dst[6] = f2tf32(v1.z); dst[7] = f2tf32(v1.w);
        }
        __syncthreads();

        #pragma unroll
        for (int ks = 0; ks < GBK; ks += 8) {
            uint32_t af[4][4];
            #pragma unroll
            for (int mt = 0; mt < 4; mt++) {
                const int m0 = warpM * 64 + mt * 16;
                af[mt][0] = As[(m0 + lr)     * AS_STR + ks + lc];
                af[mt][1] = As[(m0 + 8 + lr) * AS_STR + ks + lc];
                af[mt][2] = As[(m0 + lr)     * AS_STR + ks + 4 + lc];
                af[mt][3] = As[(m0 + 8 + lr) * AS_STR + ks + 4 + lc];
            }
            uint32_t bf[4][2];
            #pragma unroll
            for (int nt = 0; nt < 4; nt++) {
                const int n0 = warpN * 32 + nt * 8;
                bf[nt][0] = Bs[(ks + lc)     * BS_STR + n0 + lr];
                bf[nt][1] = Bs[(ks + 4 + lc) * BS_STR + n0 + lr];
            }
            #pragma unroll
            for (int mt = 0; mt < 4; mt++)
                #pragma unroll
                for (int nt = 0; nt < 4; nt++)
                    mma_tf32_16x8x8(acc[mt][nt][0], acc[mt][nt][1],
                                    acc[mt][nt][2], acc[mt][nt][3],
                                    af[mt][0], af[mt][1], af[mt][2], af[mt][3],
                                    bf[nt][0], bf[nt][1]);
        }
        __syncthreads();
    }

    #pragma unroll
    for (int mt = 0; mt < 4; mt++) {
        #pragma unroll
        for (int nt = 0; nt < 4; nt++) {
            const int n = block_col * GBN + warpN * 32 + nt * 8 + lc * 2;
            #pragma unroll
            for (int half = 0; half < 2; half++) {
                const int m = block_row * GBM + warpM * 64 + mt * 16 + lr + half * 8;
                const float v0 = acc[mt][nt][half * 2 + 0] + bias[n];
                const float v1 = acc[mt][nt][half * 2 + 1] + bias[n + 1];
                if (MODE == 0) {
                    *(float2*)&C[(size_t)m * N + n] = make_float2(v0, v1);
                } else {
                    const int b  = m >> 11;
                    const int s  = m & 2047;
                    const int h  = n >> 6;
                    const int dk = n & 63;
                    *(float2*)(C + (((size_t)(b * H_ + h)) * S_ + s) * DK_ + dk)
                        = make_float2(v0, v1);
                }
            }
        }
    }
}

// ---------------- tensor-core causal flash attention (tf32) ------------------
// 64 q-rows per block, 4 warps x 16 rows, 64-key tiles.
// smem: Ks (aliased by P), Vs — padded stride 68 for conflict-free frag reads.
#define FA_PAD 68

__global__ __launch_bounds__(128)
void flash_attn_tc_kernel(const float* __restrict__ q, const float* __restrict__ k,
                          const float* __restrict__ v, float* __restrict__ o)
{
    __shared__ uint32_t Ks[64 * FA_PAD];   // K tile, later aliased as P tile
    __shared__ uint32_t Vs[64 * FA_PAD];

    const int qt  = blockIdx.x;
    const int bh  = blockIdx.y;
    const int tid = threadIdx.x;
    const int warp = tid >> 5;
    const int lane = tid & 31;
    const int lr = lane >> 2;     // 0..7
    const int lc = lane & 3;      // 0..3
    const int q0 = qt * 64;
    const int mb = warp * 16;     // warp's q-row base within tile

    const float* qb = q + (size_t)bh * S_ * DK_;
    const float* kb = k + (size_t)bh * S_ * DK_;
    const float* vb = v + (size_t)bh * S_ * DK_;

    // ---- stage Q tile (scaled, tf32) into Ks, then preload fragments ----
    for (int idx = tid; idx < 64 * 16; idx += 128) {
        const int row = idx >> 4;
        const int c4  = (idx & 15) * 4;
        float4 t = *(const float4*)(qb + (size_t)(q0 + row) * DK_ + c4);
        uint32_t* dst = &Ks[row * FA_PAD + c4];
        dst[0] = f2tf32(t.x * SCALE_); dst[1] = f2tf32(t.y * SCALE_);
        dst[2] = f2tf32(t.z * SCALE_); dst[3] = f2tf32(t.w * SCALE_);
    }
    __syncthreads();

    uint32_t qf[8][4];
    #pragma unroll
    for (int i = 0; i < 8; i++) {
        qf[i][0] = Ks[(mb + lr)     * FA_PAD + 8 * i + lc];
        qf[i][1] = Ks[(mb + 8 + lr) * FA_PAD + 8 * i + lc];
        qf[i][2] = Ks[(mb + lr)     * FA_PAD + 8 * i + 4 + lc];
        qf[i][3] = Ks[(mb + 8 + lr) * FA_PAD + 8 * i + 4 + lc];
    }

    float oacc[8][4];
    #pragma unroll
    for (int nt = 0; nt < 8; nt++)
        #pragma unroll
        for (int c = 0; c < 4; c++) oacc[nt][c] = 0.f;
    float mrow[2] = { -INFINITY, -INFINITY };
    float lrow[2] = { 0.f, 0.f };

    for (int kt = 0; kt <= qt; kt++) {
        const int k0 = kt * 64;
        __syncthreads();   // everyone done with Ks(P)/Vs from previous iter
        // load K,V tiles as tf32
        for (int idx = tid; idx < 64 * 16; idx += 128) {
            const int row = idx >> 4;
            const int c4  = (idx & 15) * 4;
            float4 tk = *(const float4*)(kb + (size_t)(k0 + row) * DK_ + c4);
            float4 tv = *(const float4*)(vb + (size_t)(k0 + row) * DK_ + c4);
            uint32_t* dk_ = &Ks[row * FA_PAD + c4];
            uint32_t* dv_ = &Vs[row * FA_PAD + c4];
            dk_[0] = f2tf32(tk.x); dk_[1] = f2tf32(tk.y);
            dk_[2] = f2tf32(tk.z); dk_[3] = f2tf32(tk.w);
            dv_[0] = f2tf32(tv.x); dv_[1] = f2tf32(tv.y);
            dv_[2] = f2tf32(tv.z); dv_[3] = f2tf32(tv.w);
        }
        __syncthreads();

        // ---- S = Q @ K^T : 8 n-tiles (keys), 8 k-steps (dims) ----
        float s[8][4];
        #pragma unroll
        for (int nt = 0; nt < 8; nt++) {
            s[nt][0] = s[nt][1] = s[nt][2] = s[nt][3] = 0.f;
            #pragma unroll
            for (int i = 0; i < 8; i++) {
                const uint32_t b0 = Ks[(nt * 8 + lr) * FA_PAD + 8 * i + lc];
                const uint32_t b1 = Ks[(nt * 8 + lr) * FA_PAD + 8 * i + 4 + lc];
                mma_tf32_16x8x8(s[nt][0], s[nt][1], s[nt][2], s[nt][3],
                                qf[i][0], qf[i][1], qf[i][2], qf[i][3], b0, b1);
            }
        }

        // ---- causal mask (diagonal tile only) ----
        if (kt == qt) {
            const int r0 = q0 + mb + lr;      // global row of c0/c1
            const int r1 = r0 + 8;            // global row of c2/c3
            #pragma unroll
            for (int nt = 0; nt < 8; nt++) {
                const int cg = k0 + nt * 8 + 2 * lc;
                if (cg     > r0) s[nt][0] = -1e30f;
                if (cg + 1 > r0) s[nt][1] = -1e30f;
                if (cg     > r1) s[nt][2] = -1e30f;
                if (cg + 1 > r1) s[nt][3] = -1e30f;
            }
        }

        // ---- online softmax (rows lr and lr+8) ----
        float m0 = -INFINITY, m1 = -INFINITY;
        #pragma unroll
        for (int nt = 0; nt < 8; nt++) {
            m0 = fmaxf(m0, fmaxf(s[nt][0], s[nt][1]));
            m1 = fmaxf(m1, fmaxf(s[nt][2], s[nt][3]));
        }
        m0 = fmaxf(m0, __shfl_xor_sync(0xffffffffu, m0, 1));
        m0 = fmaxf(m0, __shfl_xor_sync(0xffffffffu, m0, 2));
        m1 = fmaxf(m1, __shfl_xor_sync(0xffffffffu, m1, 1));
        m1 = fmaxf(m1, __shfl_xor_sync(0xffffffffu, m1, 2));

        const float mnew0 = fmaxf(mrow[0], m0);
        const float mnew1 = fmaxf(mrow[1], m1);
        const float alpha0 = __expf(mrow[0] - mnew0);
        const float alpha1 = __expf(mrow[1] - mnew1);
        float ls0 = 0.f, ls1 = 0.f;
        #pragma unroll
        for (int nt = 0; nt < 8; nt++) {
            s[nt][0] = __expf(s[nt][0] - mnew0);
            s[nt][1] = __expf(s[nt][1] - mnew0);
            s[nt][2] = __expf(s[nt][2] - mnew1);
            s[nt][3] = __expf(s[nt][3] - mnew1);
            ls0 += s[nt][0] + s[nt][1];
            ls1 += s[nt][2] + s[nt][3];
        }
        ls0 += __shfl_xor_sync(0xffffffffu, ls0, 1);
        ls0 += __shfl_xor_sync(0xffffffffu, ls0, 2);
        ls1 += __shfl_xor_sync(0xffffffffu, ls1, 1);
        ls1 += __shfl_xor_sync(0xffffffffu, ls1, 2);
        lrow[0] = lrow[0] * alpha0 + ls0;
        lrow[1] = lrow[1] * alpha1 + ls1;
        mrow[0] = mnew0;
        mrow[1] = mnew1;
        #pragma unroll
        for (int nt = 0; nt < 8; nt++) {
            oacc[nt][0] *= alpha0; oacc[nt][1] *= alpha0;
            oacc[nt][2] *= alpha1; oacc[nt][3] *= alpha1;
        }

        // ---- store P (tf32) into Ks alias; own warp reads only its rows ----
        __syncthreads();   // all warps done reading Ks (K data)
        #pragma unroll
        for (int nt = 0; nt < 8; nt++) {
            const int c = nt * 8 + 2 * lc;
            Ks[(mb + lr)     * FA_PAD + c]     = f2tf32(s[nt][0]);
            Ks[(mb + lr)     * FA_PAD + c + 1] = f2tf32(s[nt][1]);
            Ks[(mb + 8 + lr) * FA_PAD + c]     = f2tf32(s[nt][2]);
            Ks[(mb + 8 + lr) * FA_PAD + c + 1] = f2tf32(s[nt][3]);
        }
        __syncwarp();

        // ---- O += P @ V : 8 k-steps (keys), 8 n-tiles (dk) ----
        #pragma unroll
        for (int i = 0; i < 8; i++) {
            uint32_t pf[4];
            pf[0] = Ks[(mb + lr)     * FA_PAD + 8 * i + lc];
            pf[1] = Ks[(mb + 8 + lr) * FA_PAD + 8 * i + lc];
            pf[2] = Ks[(mb + lr)     * FA_PAD + 8 * i + 4 + lc];
            pf[3] = Ks[(mb + 8 + lr) * FA_PAD + 8 * i + 4 + lc];
            #pragma unroll
            for (int nt = 0; nt < 8; nt++) {
                const uint32_t b0 = Vs[(8 * i + lc)     * FA_PAD + nt * 8 + lr];
                const uint32_t b1 = Vs[(8 * i + 4 + lc) * FA_PAD + nt * 8 + lr];
                mma_tf32_16x8x8(oacc[nt][0], oacc[nt][1], oacc[nt][2], oacc[nt][3],
                                pf[0], pf[1], pf[2], pf[3], b0, b1);
            }
        }
    }

    // ---- finalize & write to [B,S,D] ----
    const float inv0 = 1.f / lrow[0];
    const float inv1 = 1.f / lrow[1];
    const int b = bh >> 4;
    const int h = bh & 15;
    const int r0 = q0 + mb + lr;
    float* ob0 = o + ((size_t)b * S_ + r0)     * D_ + h * DK_;
    float* ob1 = o + ((size_t)b * S_ + r0 + 8) * D_ + h * DK_;
    #pragma unroll
    for (int nt = 0; nt < 8; nt++) {
        const int c = nt * 8 + 2 * lc;
        *(float2*)(ob0 + c) = make_float2(oacc[nt][0] * inv0, oacc[nt][1] * inv0);
        *(float2*)(ob1 + c) = make_float2(oacc[nt][2] * inv1, oacc[nt][3] * inv1);
    }
}

// ---------------- launch ------------------------------------------------------
extern "C" void kernel_launch(void* const* d_in, const int* in_sizes, int n_in,
                              void* d_out, int out_size)
{
    const float* Q  = (const float*)d_in[0];
    const float* K  = (const float*)d_in[1];
    const float* V  = (const float*)d_in[2];
    const float* Wq = (const float*)d_in[3];
    const float* bq = (const float*)d_in[4];
    const float* Wk = (const float*)d_in[5];
    const float* bk = (const float*)d_in[6];
    const float* Wv = (const float*)d_in[7];
    const float* bv = (const float*)d_in[8];
    const float* Wo = (const float*)d_in[9];
    const float* bo = (const float*)d_in[10];
    // d_in[11] = mask (causal, known statically; ignored)

    float *q, *k, *v, *att;
    cudaGetSymbolAddress((void**)&q,   g_q);
    cudaGetSymbolAddress((void**)&k,   g_k);
    cudaGetSymbolAddress((void**)&v,   g_v);
    cudaGetSymbolAddress((void**)&att, g_att);

    const dim3 gemm_grid(D_ / GBN, M_ROWS / GBM);   // (8, 64)
    const dim3 gemm_block(256);

    gemm_tf32_kernel<1><<<gemm_grid, gemm_block>>>(Q, Wq, bq, q, M_ROWS, D_, D_);
    gemm_tf32_kernel<1><<<gemm_grid, gemm_block>>>(K, Wk, bk, k, M_ROWS, D_, D_);
    gemm_tf32_kernel<1><<<gemm_grid, gemm_block>>>(V, Wv, bv, v, M_ROWS, D_, D_);

    const dim3 fa_grid(S_ / 64, B_ * H_);
    flash_attn_tc_kernel<<<fa_grid, 128>>>(q, k, v, att);

    gemm_tf32_kernel<0><<<gemm_grid, gemm_block>>>(att, Wo, bo, (float*)d_out,
                                                   M_ROWS, D_, D_);
}

// round 4
// speedup vs baseline: 4.2540x; 1.2475x over previous
#include <cuda_runtime.h>
#include <cuda_bf16.h>
#include <cstdint>

// Problem constants
#define B_ 4
#define S_ 2048
#define D_ 1024
#define H_ 16
#define DK_ 64
#define SCALE_ 0.125f   // 1/sqrt(64)

#define M_ROWS (B_ * S_)   // 8192

// ---------------- scratch (device globals; no allocation allowed) ----------
// All inter-kernel tensors are tf32 bits stored in uint32.
__device__ uint32_t g_qin[B_ * S_ * D_];
__device__ uint32_t g_kin[B_ * S_ * D_];
__device__ uint32_t g_vin[B_ * S_ * D_];
__device__ uint32_t g_wq[D_ * D_];
__device__ uint32_t g_wk[D_ * D_];
__device__ uint32_t g_wv[D_ * D_];
__device__ uint32_t g_wo[D_ * D_];
__device__ uint32_t g_q[B_ * H_ * S_ * DK_];    // [B,H,S,DK], pre-scaled
__device__ uint32_t g_k[B_ * H_ * S_ * DK_];
__device__ uint32_t g_v[B_ * H_ * S_ * DK_];
__device__ uint32_t g_att[B_ * S_ * D_];        // [B,S,D]

// ---------------- helpers -----------------------------------------------------
__device__ __forceinline__ uint32_t f2tf32(float f) {
    uint32_t r;
    asm("cvt.rna.tf32.f32 %0, %1;" : "=r"(r) : "f"(f));
    return r;
}

__device__ __forceinline__ void mma_tf32_16x8x8(
    float& c0, float& c1, float& c2, float& c3,
    uint32_t a0, uint32_t a1, uint32_t a2, uint32_t a3,
    uint32_t b0, uint32_t b1)
{
    asm volatile(
        "mma.sync.aligned.m16n8k8.row.col.f32.tf32.tf32.f32 "
        "{%0,%1,%2,%3}, {%4,%5,%6,%7}, {%8,%9}, {%0,%1,%2,%3};"
        : "+f"(c0), "+f"(c1), "+f"(c2), "+f"(c3)
        : "r"(a0), "r"(a1), "r"(a2), "r"(a3), "r"(b0), "r"(b1));
}

__device__ __forceinline__ void cp_async16(uint32_t smem_dst, const void* gsrc) {
    asm volatile("cp.async.cg.shared.global [%0], [%1], 16;"
                 :: "r"(smem_dst), "l"(gsrc));
}
__device__ __forceinline__ void cp_commit() {
    asm volatile("cp.async.commit_group;");
}
__device__ __forceinline__ void cp_wait0() {
    asm volatile("cp.async.wait_group 0;");
}
__device__ __forceinline__ uint32_t smaddr(const void* p) {
    return (uint32_t)__cvta_generic_to_shared(p);
}

// ---------------- fp32 -> tf32 conversion kernel ------------------------------
__global__ __launch_bounds__(256)
void conv_tf32_kernel(const float4* __restrict__ in, uint4* __restrict__ out, int n4)
{
    const int i = blockIdx.x * 256 + threadIdx.x;
    if (i < n4) {
        float4 v = in[i];
        uint4 r;
        r.x = f2tf32(v.x); r.y = f2tf32(v.y);
        r.z = f2tf32(v.z); r.w = f2tf32(v.w);
        out[i] = r;
    }
}

// ---------------- tf32 tensor-core GEMM (cp.async double-buffered) ------------
// C = A[M,K] @ W[K,N] + bias.  A, W hold tf32 bits.
// MODE 0: C = float*, row-major [M,N]
// MODE 1: C = uint32* tf32 bits, [B,H,S,DK] layout, value scaled by out_scale.
#define GBM 128
#define GBN 128
#define GBK 16
#define AS_STR (GBK + 4)    // 20
#define BS_STR (GBN + 8)    // 136

template <int MODE>
__global__ __launch_bounds__(256)
void gemm_tf32_kernel(const uint32_t* __restrict__ A, const uint32_t* __restrict__ W,
                      const float* __restrict__ bias, void* __restrict__ Cout,
                      int M, int N, int K, float out_scale)
{
    __shared__ uint32_t As[2][GBM * AS_STR];
    __shared__ uint32_t Bs[2][GBK * BS_STR];

    const int tid  = threadIdx.x;
    const int warp = tid >> 5;
    const int lane = tid & 31;
    const int warpM = warp >> 2;
    const int warpN = warp & 3;
    const int lr = lane >> 2;
    const int lc = lane & 3;

    const int block_row = blockIdx.y;
    const int block_col = blockIdx.x;

    const uint32_t* Ab = A + (size_t)block_row * GBM * K;
    const uint32_t* Wb = W + block_col * GBN;

    float acc[4][4][4];
    #pragma unroll
    for (int mt = 0; mt < 4; mt++)
        #pragma unroll
        for (int nt = 0; nt < 4; nt++)
            #pragma unroll
            for (int r = 0; r < 4; r++) acc[mt][nt][r] = 0.f;

    // stage loader: 512 16B-chunks for A (128x16) and B (16x128); 2 each/thread
    auto load_stage = [&](int k0, int buf) {
        #pragma unroll
        for (int u = 0; u < 2; u++) {
            const int flat = tid + u * 256;
            const int ar = flat >> 2, ac = (flat & 3) * 4;
            cp_async16(smaddr(&As[buf][ar * AS_STR + ac]),
                       Ab + (size_t)ar * K + k0 + ac);
            const int br = flat >> 5, bc = (flat & 31) * 4;
            cp_async16(smaddr(&Bs[buf][br * BS_STR + bc]),
                       Wb + (size_t)(k0 + br) * N + bc);
        }
    };

    const int NK = K / GBK;
    load_stage(0, 0);
    cp_commit();

    for (int it = 0; it < NK; it++) {
        cp_wait0();
        __syncthreads();
        if (it + 1 < NK) { load_stage((it + 1) * GBK, (it + 1) & 1); cp_commit(); }

        const uint32_t* As_s = As[it & 1];
        const uint32_t* Bs_s = Bs[it & 1];

        #pragma unroll
        for (int ks = 0; ks < GBK; ks += 8) {
            uint32_t af[4][4];
            #pragma unroll
            for (int mt = 0; mt < 4; mt++) {
                const int m0 = warpM * 64 + mt * 16;
                af[mt][0] = As_s[(m0 + lr)     * AS_STR + ks + lc];
                af[mt][1] = As_s[(m0 + 8 + lr) * AS_STR + ks + lc];
                af[mt][2] = As_s[(m0 + lr)     * AS_STR + ks + 4 + lc];
                af[mt][3] = As_s[(m0 + 8 + lr) * AS_STR + ks + 4 + lc];
            }
            uint32_t bf[4][2];
            #pragma unroll
            for (int nt = 0; nt < 4; nt++) {
                const int n0 = warpN * 32 + nt * 8;
                bf[nt][0] = Bs_s[(ks + lc)     * BS_STR + n0 + lr];
                bf[nt][1] = Bs_s[(ks + 4 + lc) * BS_STR + n0 + lr];
            }
            #pragma unroll
            for (int mt = 0; mt < 4; mt++)
                #pragma unroll
                for (int nt = 0; nt < 4; nt++)
                    mma_tf32_16x8x8(acc[mt][nt][0], acc[mt][nt][1],
                                    acc[mt][nt][2], acc[mt][nt][3],
                                    af[mt][0], af[mt][1], af[mt][2], af[mt][3],
                                    bf[nt][0], bf[nt][1]);
        }
    }

    #pragma unroll
    for (int mt = 0; mt < 4; mt++) {
        #pragma unroll
        for (int nt = 0; nt < 4; nt++) {
            const int n = block_col * GBN + warpN * 32 + nt * 8 + lc * 2;
            #pragma unroll
            for (int half = 0; half < 2; half++) {
                const int m = block_row * GBM + warpM * 64 + mt * 16 + lr + half * 8;
                const float v0 = acc[mt][nt][half * 2 + 0] + bias[n];
                const float v1 = acc[mt][nt][half * 2 + 1] + bias[n + 1];
                if (MODE == 0) {
                    float* C = (float*)Cout;
                    *(float2*)&C[(size_t)m * N + n] = make_float2(v0, v1);
                } else {
                    uint32_t* C = (uint32_t*)Cout;
                    const int b  = m >> 11;
                    const int s  = m & 2047;
                    const int h  = n >> 6;
                    const int dk = n & 63;
                    uint2 w;
                    w.x = f2tf32(v0 * out_scale);
                    w.y = f2tf32(v1 * out_scale);
                    *(uint2*)(C + (((size_t)(b * H_ + h)) * S_ + s) * DK_ + dk) = w;
                }
            }
        }
    }
}

// ---------------- tensor-core causal flash attention (tf32, cp.async) ---------
// 64 q-rows per block, 4 warps x 16 rows, 64-key tiles, double-buffered K/V.
// q,k,v hold tf32 bits (q pre-scaled). Output written as tf32 bits to [B,S,D].
#define FA_PAD 68
#define FA_TILE (64 * FA_PAD)

__global__ __launch_bounds__(128)
void flash_attn_tc_kernel(const uint32_t* __restrict__ q, const uint32_t* __restrict__ k,
                          const uint32_t* __restrict__ v, uint32_t* __restrict__ o)
{
    extern __shared__ uint32_t sm[];
    uint32_t* KsBuf[2] = { sm,               sm + FA_TILE };
    uint32_t* VsBuf[2] = { sm + 2 * FA_TILE, sm + 3 * FA_TILE };

    const int qt  = blockIdx.x;
    const int bh  = blockIdx.y;
    const int tid = threadIdx.x;
    const int warp = tid >> 5;
    const int lane = tid & 31;
    const int lr = lane >> 2;
    const int lc = lane & 3;
    const int q0 = qt * 64;
    const int mb = warp * 16;

    const uint32_t* qb = q + (size_t)bh * S_ * DK_;
    const uint32_t* kb = k + (size_t)bh * S_ * DK_;
    const uint32_t* vb = v + (size_t)bh * S_ * DK_;

    // tile copy: 64 rows x 64 words = 1024 16B-chunks; 8 per thread
    auto load_tile = [&](const uint32_t* gsrc, uint32_t* sdst) {
        #pragma unroll
        for (int i = 0; i < 8; i++) {
            const int flat = tid + 128 * i;
            const int row = flat >> 4;
            const int c4  = (flat & 15) * 4;
            cp_async16(smaddr(sdst + row * FA_PAD + c4), gsrc + row * 64 + c4);
        }
    };

    // ---- stage Q tile into VsBuf[0], extract fragments ----
    load_tile(qb + (size_t)q0 * DK_, VsBuf[0]);
    cp_commit();
    cp_wait0();
    __syncthreads();

    uint32_t qf[8][4];
    #pragma unroll
    for (int i = 0; i < 8; i++) {
        qf[i][0] = VsBuf[0][(mb + lr)     * FA_PAD + 8 * i + lc];
        qf[i][1] = VsBuf[0][(mb + 8 + lr) * FA_PAD + 8 * i + lc];
        qf[i][2] = VsBuf[0][(mb + lr)     * FA_PAD + 8 * i + 4 + lc];
        qf[i][3] = VsBuf[0][(mb + 8 + lr) * FA_PAD + 8 * i + 4 + lc];
    }
    __syncthreads();   // all qf reads done before VsBuf[0] is overwritten

    float oacc[8][4];
    #pragma unroll
    for (int nt = 0; nt < 8; nt++)
        #pragma unroll
        for (int c = 0; c < 4; c++) oacc[nt][c] = 0.f;
    float mrow[2] = { -INFINITY, -INFINITY };
    float lrow[2] = { 0.f, 0.f };

    // prologue: tile 0
    load_tile(kb, KsBuf[0]);
    load_tile(vb, VsBuf[0]);
    cp_commit();

    for (int kt = 0; kt <= qt; kt++) {
        const int cur = kt & 1;
        cp_wait0();
        __syncthreads();   // tile kt visible to all; prior iter fully consumed
        if (kt < qt) {
            load_tile(kb + (size_t)(kt + 1) * 64 * DK_, KsBuf[cur ^ 1]);
            load_tile(vb + (size_t)(kt + 1) * 64 * DK_, VsBuf[cur ^ 1]);
            cp_commit();
        }
        const uint32_t* Ks = KsBuf[cur];
        const uint32_t* Vs = VsBuf[cur];
        uint32_t* Ps = KsBuf[cur];   // P aliases current K buffer

        // ---- S = Q @ K^T ----
        float s[8][4];
        #pragma unroll
        for (int nt = 0; nt < 8; nt++) {
            s[nt][0] = s[nt][1] = s[nt][2] = s[nt][3] = 0.f;
            #pragma unroll
            for (int i = 0; i < 8; i++) {
                const uint32_t b0 = Ks[(nt * 8 + lr) * FA_PAD + 8 * i + lc];
                const uint32_t b1 = Ks[(nt * 8 + lr) * FA_PAD + 8 * i + 4 + lc];
                mma_tf32_16x8x8(s[nt][0], s[nt][1], s[nt][2], s[nt][3],
                                qf[i][0], qf[i][1], qf[i][2], qf[i][3], b0, b1);
            }
        }

        // ---- causal mask (diagonal tile only) ----
        if (kt == qt) {
            const int k0 = kt * 64;
            const int r0 = q0 + mb + lr;
            const int r1 = r0 + 8;
            #pragma unroll
            for (int nt = 0; nt < 8; nt++) {
                const int cg = k0 + nt * 8 + 2 * lc;
                if (cg     > r0) s[nt][0] = -1e30f;
                if (cg + 1 > r0) s[nt][1] = -1e30f;
                if (cg     > r1) s[nt][2] = -1e30f;
                if (cg + 1 > r1) s[nt][3] = -1e30f;
            }
        }

        // ---- online softmax ----
        float m0 = -INFINITY, m1 = -INFINITY;
        #pragma unroll
        for (int nt = 0; nt < 8; nt++) {
            m0 = fmaxf(m0, fmaxf(s[nt][0], s[nt][1]));
            m1 = fmaxf(m1, fmaxf(s[nt][2], s[nt][3]));
        }
        m0 = fmaxf(m0, __shfl_xor_sync(0xffffffffu, m0, 1));
        m0 = fmaxf(m0, __shfl_xor_sync(0xffffffffu, m0, 2));
        m1 = fmaxf(m1, __shfl_xor_sync(0xffffffffu, m1, 1));
        m1 = fmaxf(m1, __shfl_xor_sync(0xffffffffu, m1, 2));

        const float mnew0 = fmaxf(mrow[0], m0);
        const float mnew1 = fmaxf(mrow[1], m1);
        const float alpha0 = __expf(mrow[0] - mnew0);
        const float alpha1 = __expf(mrow[1] - mnew1);
        float ls0 = 0.f, ls1 = 0.f;
        #pragma unroll
        for (int nt = 0; nt < 8; nt++) {
            s[nt][0] = __expf(s[nt][0] - mnew0);
            s[nt][1] = __expf(s[nt][1] - mnew0);
            s[nt][2] = __expf(s[nt][2] - mnew1);
            s[nt][3] = __expf(s[nt][3] - mnew1);
            ls0 += s[nt][0] + s[nt][1];
            ls1 += s[nt][2] + s[nt][3];
        }
        ls0 += __shfl_xor_sync(0xffffffffu, ls0, 1);
        ls0 += __shfl_xor_sync(0xffffffffu, ls0, 2);
        ls1 += __shfl_xor_sync(0xffffffffu, ls1, 1);
        ls1 += __shfl_xor_sync(0xffffffffu, ls1, 2);
        lrow[0] = lrow[0] * alpha0 + ls0;
        lrow[1] = lrow[1] * alpha1 + ls1;
        mrow[0] = mnew0;
        mrow[1] = mnew1;
        #pragma unroll
        for (int nt = 0; nt < 8; nt++) {
            oacc[nt][0] *= alpha0; oacc[nt][1] *= alpha0;
            oacc[nt][2] *= alpha1; oacc[nt][3] *= alpha1;
        }

        // ---- store P (tf32) into K alias; own warp rows only ----
        __syncthreads();   // all warps done reading K data from Ks
        #pragma unroll
        for (int nt = 0; nt < 8; nt++) {
            const int c = nt * 8 + 2 * lc;
            Ps[(mb + lr)     * FA_PAD + c]     = f2tf32(s[nt][0]);
            Ps[(mb + lr)     * FA_PAD + c + 1] = f2tf32(s[nt][1]);
            Ps[(mb + 8 + lr) * FA_PAD + c]     = f2tf32(s[nt][2]);
            Ps[(mb + 8 + lr) * FA_PAD + c + 1] = f2tf32(s[nt][3]);
        }
        __syncwarp();

        // ---- O += P @ V ----
        #pragma unroll
        for (int i = 0; i < 8; i++) {
            uint32_t pf[4];
            pf[0] = Ps[(mb + lr)     * FA_PAD + 8 * i + lc];
            pf[1] = Ps[(mb + 8 + lr) * FA_PAD + 8 * i + lc];
            pf[2] = Ps[(mb + lr)     * FA_PAD + 8 * i + 4 + lc];
            pf[3] = Ps[(mb + 8 + lr) * FA_PAD + 8 * i + 4 + lc];
            #pragma unroll
            for (int nt = 0; nt < 8; nt++) {
                const uint32_t b0 = Vs[(8 * i + lc)     * FA_PAD + nt * 8 + lr];
                const uint32_t b1 = Vs[(8 * i + 4 + lc) * FA_PAD + nt * 8 + lr];
                mma_tf32_16x8x8(oacc[nt][0], oacc[nt][1], oacc[nt][2], oacc[nt][3],
                                pf[0], pf[1], pf[2], pf[3], b0, b1);
            }
        }
    }

    // ---- finalize & write tf32 bits to [B,S,D] ----
    const float inv0 = 1.f / lrow[0];
    const float inv1 = 1.f / lrow[1];
    const int b = bh >> 4;
    const int h = bh & 15;
    const int r0 = q0 + mb + lr;
    uint32_t* ob0 = o + ((size_t)b * S_ + r0)     * D_ + h * DK_;
    uint32_t* ob1 = o + ((size_t)b * S_ + r0 + 8) * D_ + h * DK_;
    #pragma unroll
    for (int nt = 0; nt < 8; nt++) {
        const int c = nt * 8 + 2 * lc;
        uint2 w0, w1;
        w0.x = f2tf32(oacc[nt][0] * inv0); w0.y = f2tf32(oacc[nt][1] * inv0);
        w1.x = f2tf32(oacc[nt][2] * inv1); w1.y = f2tf32(oacc[nt][3] * inv1);
        *(uint2*)(ob0 + c) = w0;
        *(uint2*)(ob1 + c) = w1;
    }
}

// ---------------- launch ------------------------------------------------------
extern "C" void kernel_launch(void* const* d_in, const int* in_sizes, int n_in,
                              void* d_out, int out_size)
{
    const float* Q  = (const float*)d_in[0];
    const float* K  = (const float*)d_in[1];
    const float* V  = (const float*)d_in[2];
    const float* Wq = (const float*)d_in[3];
    const float* bq = (const float*)d_in[4];
    const float* Wk = (const float*)d_in[5];
    const float* bk = (const float*)d_in[6];
    const float* Wv = (const float*)d_in[7];
    const float* bv = (const float*)d_in[8];
    const float* Wo = (const float*)d_in[9];
    const float* bo = (const float*)d_in[10];
    // d_in[11] = mask (causal, known statically; ignored)

    uint32_t *qin, *kin, *vin, *wq, *wk, *wv, *wo, *q, *k, *v, *att;
    cudaGetSymbolAddress((void**)&qin, g_qin);
    cudaGetSymbolAddress((void**)&kin, g_kin);
    cudaGetSymbolAddress((void**)&vin, g_vin);
    cudaGetSymbolAddress((void**)&wq,  g_wq);
    cudaGetSymbolAddress((void**)&wk,  g_wk);
    cudaGetSymbolAddress((void**)&wv,  g_wv);
    cudaGetSymbolAddress((void**)&wo,  g_wo);
    cudaGetSymbolAddress((void**)&q,   g_q);
    cudaGetSymbolAddress((void**)&k,   g_k);
    cudaGetSymbolAddress((void**)&v,   g_v);
    cudaGetSymbolAddress((void**)&att, g_att);

    // fp32 -> tf32 pre-conversion
    const int n4_in = (B_ * S_ * D_) / 4;   // 2,097,152
    const int n4_w  = (D_ * D_) / 4;        // 262,144
    conv_tf32_kernel<<<(n4_in + 255) / 256, 256>>>((const float4*)Q,  (uint4*)qin, n4_in);
    conv_tf32_kernel<<<(n4_in + 255) / 256, 256>>>((const float4*)K,  (uint4*)kin, n4_in);
    conv_tf32_kernel<<<(n4_in + 255) / 256, 256>>>((const float4*)V,  (uint4*)vin, n4_in);
    conv_tf32_kernel<<<(n4_w  + 255) / 256, 256>>>((const float4*)Wq, (uint4*)wq,  n4_w);
    conv_tf32_kernel<<<(n4_w  + 255) / 256, 256>>>((const float4*)Wk, (uint4*)wk,  n4_w);
    conv_tf32_kernel<<<(n4_w  + 255) / 256, 256>>>((const float4*)Wv, (uint4*)wv,  n4_w);
    conv_tf32_kernel<<<(n4_w  + 255) / 256, 256>>>((const float4*)Wo, (uint4*)wo,  n4_w);

    const dim3 gemm_grid(D_ / GBN, M_ROWS / GBM);   // (8, 64)
    const dim3 gemm_block(256);

    // QKV projections -> tf32 [B,H,S,DK]; Q pre-scaled by 1/sqrt(dk)
    gemm_tf32_kernel<1><<<gemm_grid, gemm_block>>>(qin, wq, bq, q, M_ROWS, D_, D_, SCALE_);
    gemm_tf32_kernel<1><<<gemm_grid, gemm_block>>>(kin, wk, bk, k, M_ROWS, D_, D_, 1.0f);
    gemm_tf32_kernel<1><<<gemm_grid, gemm_block>>>(vin, wv, bv, v, M_ROWS, D_, D_, 1.0f);

    // causal flash attention -> tf32 [B,S,D]
    static const int FA_SMEM = 4 * FA_TILE * (int)sizeof(uint32_t);   // 69,632 B
    cudaFuncSetAttribute(flash_attn_tc_kernel,
                         cudaFuncAttributeMaxDynamicSharedMemorySize, FA_SMEM);
    const dim3 fa_grid(S_ / 64, B_ * H_);
    flash_attn_tc_kernel<<<fa_grid, 128, FA_SMEM>>>(q, k, v, att);

    // output projection -> d_out (fp32)
    gemm_tf32_kernel<0><<<gemm_grid, gemm_block>>>(att, wo, bo, d_out,
                                                   M_ROWS, D_, D_, 1.0f);
}